// round 1
// baseline (speedup 1.0000x reference)
#include <cuda_runtime.h>
#include <cuda_bf16.h>
#include <cstdint>

// TopK(k=64) + sigmoid scatter over rows of [N, 4096] fp32.
// One CTA per row. Exact selection via 4-pass radix-256 on monotonic keys.

constexpr int D = 4096;     // row length
constexpr int T = 256;      // threads per CTA
constexpr int KSEL = 64;    // top-k budget
constexpr int EPT = D / T;  // elements per thread (16)

__device__ __forceinline__ uint32_t float_to_key(float f) {
    uint32_t u = __float_as_uint(f);
    // monotonic: larger float -> larger unsigned key
    return (u & 0x80000000u) ? ~u : (u | 0x80000000u);
}

__device__ __forceinline__ float key_to_float(uint32_t k) {
    uint32_t u = (k & 0x80000000u) ? (k ^ 0x80000000u) : ~k;
    return __uint_as_float(u);
}

__global__ __launch_bounds__(T, 8)
void topk_sigmoid_kernel(const float* __restrict__ x,
                         float* __restrict__ out) {
    __shared__ uint32_t skey[D];
    __shared__ int hist[256];
    __shared__ uint32_t s_prefix;
    __shared__ int s_remk;
    __shared__ int s_eqcnt;

    const int row = blockIdx.x;
    const int tid = threadIdx.x;
    const float4* __restrict__ x4 = reinterpret_cast<const float4*>(x + (size_t)row * D);

    // ---- load row, convert to monotonic keys in shared ----
    #pragma unroll
    for (int i = tid; i < D / 4; i += T) {
        float4 v = x4[i];
        skey[4 * i + 0] = float_to_key(v.x);
        skey[4 * i + 1] = float_to_key(v.y);
        skey[4 * i + 2] = float_to_key(v.z);
        skey[4 * i + 3] = float_to_key(v.w);
    }
    __syncthreads();

    // ---- 4-pass radix-256 select of the KSEL-th largest key ----
    uint32_t prefix = 0;
    int remk = KSEL;

    #pragma unroll
    for (int pass = 0; pass < 4; ++pass) {
        const int shift = 24 - 8 * pass;
        const uint32_t pmask = (pass == 0) ? 0u : (0xFFFFFFFFu << (shift + 8));

        if (tid < 256) hist[tid] = 0;
        __syncthreads();

        #pragma unroll
        for (int i = tid; i < D; i += T) {
            uint32_t kk = skey[i];
            bool cand = ((kk & pmask) == prefix);
            unsigned act = __ballot_sync(0xFFFFFFFFu, cand);
            if (cand) {
                uint32_t bin = (kk >> shift) & 0xFFu;
                // warp-aggregate: one atomic per distinct bin per warp
                unsigned peers = __match_any_sync(act, bin);
                int leader = __ffs(peers) - 1;
                if ((tid & 31) == leader)
                    atomicAdd(&hist[bin], __popc(peers));
            }
        }
        __syncthreads();

        if (tid == 0) {
            int cum = 0;
            int b = 255;
            for (; b > 0; --b) {
                int c = hist[b];
                if (cum + c >= remk) break;
                cum += c;
            }
            s_prefix = prefix | ((uint32_t)b << shift);
            s_remk = remk - cum;
        }
        __syncthreads();
        prefix = s_prefix;
        remk = s_remk;
        __syncthreads();  // protect hist before next pass zeroes it
    }

    const uint32_t thr = prefix;  // exact KSEL-th largest key

    // ---- count ties at threshold ----
    if (tid == 0) s_eqcnt = 0;
    __syncthreads();
    {
        int loc = 0;
        #pragma unroll
        for (int i = tid; i < D; i += T)
            if (skey[i] == thr) loc++;
        // warp reduce then one atomic per warp
        #pragma unroll
        for (int o = 16; o > 0; o >>= 1) loc += __shfl_down_sync(0xFFFFFFFFu, loc, o);
        if ((tid & 31) == 0 && loc) atomicAdd(&s_eqcnt, loc);
    }
    __syncthreads();
    const int neq = s_eqcnt;

    // ---- write output: sigmoid for selected, 0 otherwise (coalesced) ----
    float* __restrict__ orow = out + (size_t)row * D;
    #pragma unroll
    for (int i = tid; i < D; i += T) {
        uint32_t kk = skey[i];
        bool inc;
        if (kk > thr) {
            inc = true;
        } else if (kk < thr) {
            inc = false;
        } else if (neq == remk) {
            inc = true;  // all ties fit: the common (no-duplicate) case
        } else {
            // exact tie-break: take the `remk` equal keys with smallest index
            int r = 0;
            for (int j = 0; j < i; ++j)
                if (skey[j] == thr) r++;
            inc = (r < remk);
        }
        float f = key_to_float(kk);
        orow[i] = inc ? __frcp_rn(1.0f + __expf(-f)) : 0.0f;
    }
}

extern "C" void kernel_launch(void* const* d_in, const int* in_sizes, int n_in,
                              void* d_out, int out_size) {
    const float* x = (const float*)d_in[0];
    float* out = (float*)d_out;
    int rows = in_sizes[0] / D;
    topk_sigmoid_kernel<<<rows, T>>>(x, out);
}

// round 2
// speedup vs baseline: 2.3584x; 2.3584x over previous
#include <cuda_runtime.h>
#include <cuda_bf16.h>
#include <cstdint>

// TopK(k=64) + sigmoid scatter over rows of [16384, 4096] fp32.
// One CTA per row. Exact 4-pass radix-256 select on monotonic uint32 keys.
// vs R1: fused pass-0 histogram into load, parallel suffix-scan bin search,
// cheap predicated histogram for passes 1-3, tie count for free from pass 3.

constexpr int D = 4096;     // row length
constexpr int T = 256;      // threads per CTA
constexpr int KSEL = 64;    // top-k budget

__device__ __forceinline__ uint32_t f2k(float f) {
    uint32_t u = __float_as_uint(f);
    return (u & 0x80000000u) ? ~u : (u | 0x80000000u);  // monotonic key
}
__device__ __forceinline__ float k2f(uint32_t k) {
    uint32_t u = (k & 0x80000000u) ? (k ^ 0x80000000u) : ~k;
    return __uint_as_float(u);
}
__device__ __forceinline__ float sigm(float f) {
    return __frcp_rn(1.0f + __expf(-f));
}

__global__ __launch_bounds__(T, 8)
void topk_sigmoid_kernel(const float* __restrict__ x,
                         float* __restrict__ out) {
    __shared__ __align__(16) uint32_t skey[D];
    __shared__ int hist[256];
    __shared__ int warpsum[8];
    __shared__ uint32_t s_bin;
    __shared__ int s_remk;
    __shared__ int s_neq;

    const int row  = blockIdx.x;
    const int tid  = threadIdx.x;
    const int lane = tid & 31;
    const int wrp  = tid >> 5;
    const float4* __restrict__ x4 =
        reinterpret_cast<const float4*>(x) + (size_t)row * (D / 4);

    hist[tid] = 0;  // 256 bins, T == 256
    __syncthreads();

    // ---- load + convert + store keys + pass-0 histogram (top byte) ----
    // Warp-aggregated atomics: Gaussian data clusters in ~10 exponent bins,
    // so aggregation turns serialization into reduction.
    #pragma unroll
    for (int j = 0; j < 4; ++j) {
        int v = tid + T * j;
        float4 f = x4[v];
        uint4 k;
        k.x = f2k(f.x); k.y = f2k(f.y); k.z = f2k(f.z); k.w = f2k(f.w);
        reinterpret_cast<uint4*>(skey)[v] = k;
        #pragma unroll
        for (int e = 0; e < 4; ++e) {
            uint32_t kk = (e == 0) ? k.x : (e == 1) ? k.y : (e == 2) ? k.z : k.w;
            uint32_t b = kk >> 24;
            unsigned peers = __match_any_sync(0xFFFFFFFFu, b);
            if (lane == (__ffs(peers) - 1))
                atomicAdd(&hist[b], __popc(peers));
        }
    }
    __syncthreads();

    // ---- 4-pass radix-256 select (pass 0 hist already built) ----
    uint32_t prefix = 0;
    int remk = KSEL;

    #pragma unroll
    for (int pass = 0; pass < 4; ++pass) {
        const int shift = 24 - 8 * pass;

        if (pass > 0) {
            const uint32_t pmask = 0xFFFFFFFFu << (shift + 8);
            hist[tid] = 0;
            __syncthreads();
            // Only ~100-650 candidates match the prefix; predicated atomic,
            // bins (mantissa bits) are uniform -> negligible contention.
            #pragma unroll
            for (int i = tid; i < D; i += T) {
                uint32_t kk = skey[i];
                if ((kk & pmask) == prefix)
                    atomicAdd(&hist[(kk >> shift) & 0xFFu], 1);
            }
            __syncthreads();
        }

        // ---- parallel suffix-scan bin search (replaces serial tid-0 loop) ----
        {
            int h = hist[tid];
            int s = h;  // inclusive suffix sum within warp (lanes >= mine)
            #pragma unroll
            for (int o = 1; o < 32; o <<= 1) {
                int vv = __shfl_down_sync(0xFFFFFFFFu, s, o);
                if (lane + o < 32) s += vv;
            }
            if (lane == 0) warpsum[wrp] = s;
            __syncthreads();
            int above = 0;
            #pragma unroll
            for (int w = 0; w < 8; ++w)
                if (w > wrp) above += warpsum[w];
            int G = above + (s - h);  // count in bins strictly greater than tid
            if (G < remk && G + h >= remk) {  // exactly one thread matches
                s_bin  = (uint32_t)tid;
                s_remk = remk - G;
                s_neq  = h;
            }
        }
        __syncthreads();
        prefix |= (s_bin << shift);
        remk = s_remk;
        // no extra barrier needed: next write to hist/s_* is >= 2 barriers away
    }

    const uint32_t thr = prefix;       // exact KSEL-th largest key
    const int neq = s_neq;             // count of keys == thr (from pass 3 hist)
    const bool allt = (neq == remk);   // all ties included (the ~always case)

    // ---- output: sigmoid for selected, 0 otherwise (128-bit coalesced) ----
    float* __restrict__ orow = out + (size_t)row * D;
    #pragma unroll
    for (int j = 0; j < 4; ++j) {
        int v = tid + T * j;
        uint4 k = reinterpret_cast<const uint4*>(skey)[v];
        float4 r;
        #pragma unroll
        for (int e = 0; e < 4; ++e) {
            uint32_t kk = (e == 0) ? k.x : (e == 1) ? k.y : (e == 2) ? k.z : k.w;
            float f = 0.0f;
            if (kk >= thr) {                     // ~64/4096 elements
                bool inc = (kk > thr) || allt;
                if (!inc) {                      // exact tie-break, ~never taken
                    int idx = 4 * v + e;
                    int rk = 0;
                    for (int q = 0; q < idx; ++q) rk += (skey[q] == thr);
                    inc = (rk < remk);           // lowest-index ties first
                }
                if (inc) f = sigm(k2f(kk));
            }
            ((float*)&r)[e] = f;
        }
        reinterpret_cast<float4*>(orow)[v] = r;
    }
}

extern "C" void kernel_launch(void* const* d_in, const int* in_sizes, int n_in,
                              void* d_out, int out_size) {
    const float* x = (const float*)d_in[0];
    float* out = (float*)d_out;
    int rows = in_sizes[0] / D;
    topk_sigmoid_kernel<<<rows, T>>>(x, out);
}

// round 3
// speedup vs baseline: 2.6075x; 1.1056x over previous
#include <cuda_runtime.h>
#include <cuda_bf16.h>
#include <cstdint>

// TopK(k=64) + sigmoid scatter over rows of [16384, 4096] fp32.
// One CTA per row. Exact 4-pass radix-256 select on monotonic uint32 keys.
// vs R2: warp0-only bin search, vectorized LDS.128 pass scans, 2-instr key
// transform, LOP3-fused prefix match, predicated unaggregated pass atomics.

constexpr int D = 4096;     // row length
constexpr int T = 256;      // threads per CTA
constexpr int KSEL = 64;    // top-k budget

__device__ __forceinline__ uint32_t f2k(uint32_t u) {
    // monotonic: larger float -> larger unsigned key (SHF + LOP3)
    return u ^ ((uint32_t)((int)u >> 31) | 0x80000000u);
}
__device__ __forceinline__ float k2f(uint32_t k) {
    uint32_t m = (uint32_t)((int)k >> 31);  // all-ones if key came from positive
    return __uint_as_float(k ^ (~m | 0x80000000u));
}
__device__ __forceinline__ float sigm(float f) {
    return __frcp_rn(1.0f + __expf(-f));
}

__global__ __launch_bounds__(T, 8)
void topk_sigmoid_kernel(const float* __restrict__ x,
                         float* __restrict__ out) {
    __shared__ __align__(16) uint32_t skey[D];
    __shared__ __align__(16) int hist[256];
    __shared__ uint32_t s_bin;
    __shared__ int s_remk;
    __shared__ int s_neq;

    const int row  = blockIdx.x;
    const int tid  = threadIdx.x;
    const int lane = tid & 31;
    const int wrp  = tid >> 5;
    const uint4* __restrict__ x4 =
        reinterpret_cast<const uint4*>(x) + (size_t)row * (D / 4);

    hist[tid] = 0;
    __syncthreads();

    // ---- load + key-convert + store + pass-0 histogram (top byte) ----
    // match_any aggregation: Gaussian clusters in ~8 exponent bins per warp,
    // so this turns same-address atomic serialization into one atomic/bin.
    #pragma unroll
    for (int j = 0; j < 4; ++j) {
        int v = tid + T * j;
        uint4 u = x4[v];
        uint4 k;
        k.x = f2k(u.x); k.y = f2k(u.y); k.z = f2k(u.z); k.w = f2k(u.w);
        reinterpret_cast<uint4*>(skey)[v] = k;
        #pragma unroll
        for (int e = 0; e < 4; ++e) {
            uint32_t kk = (e == 0) ? k.x : (e == 1) ? k.y : (e == 2) ? k.z : k.w;
            uint32_t b = kk >> 24;
            unsigned peers = __match_any_sync(0xFFFFFFFFu, b);
            if ((peers & ((1u << lane) - 1u)) == 0)  // lowest-lane leader
                atomicAdd(&hist[b], __popc(peers));
        }
    }
    __syncthreads();

    // ---- warp0-only bin search over hist[256]; writes s_bin/s_remk/s_neq ----
    auto binsearch = [&](int remk) {
        if (wrp == 0) {
            int4 a = reinterpret_cast<const int4*>(hist)[lane * 2];
            int4 b = reinterpret_cast<const int4*>(hist)[lane * 2 + 1];
            int h[8] = {a.x, a.y, a.z, a.w, b.x, b.y, b.z, b.w};
            int t[8];
            t[7] = h[7];
            #pragma unroll
            for (int j = 6; j >= 0; --j) t[j] = h[j] + t[j + 1];
            int total = t[0];
            int s = total;  // inclusive suffix over lanes >= mine
            #pragma unroll
            for (int o = 1; o < 32; o <<= 1) {
                int v = __shfl_down_sync(0xFFFFFFFFu, s, o);
                if (lane + o < 32) s += v;
            }
            int above = s - total;  // counts in bins owned by higher lanes
            #pragma unroll
            for (int j = 0; j < 8; ++j) {
                int G = above + t[j] - h[j];  // count strictly above bin (lane,j)
                if (G < remk && G + h[j] >= remk) {  // exactly one (lane,j)
                    s_bin  = (uint32_t)(lane * 8 + j);
                    s_remk = remk - G;
                    s_neq  = h[j];
                }
            }
        }
    };

    uint32_t prefix;
    int remk;

    binsearch(KSEL);
    __syncthreads();
    prefix = s_bin << 24;
    remk = s_remk;
    hist[tid] = 0;
    __syncthreads();

    // ---- passes 1-3: vectorized scan, predicated rare atomics ----
    #pragma unroll
    for (int pass = 1; pass < 4; ++pass) {
        const int shift = 24 - 8 * pass;
        const uint32_t pmask = 0xFFFFFFFFu << (shift + 8);
        #pragma unroll
        for (int j = 0; j < 4; ++j) {
            uint4 k = reinterpret_cast<const uint4*>(skey)[tid + T * j];
            #pragma unroll
            for (int e = 0; e < 4; ++e) {
                uint32_t kk = (e == 0) ? k.x : (e == 1) ? k.y : (e == 2) ? k.z : k.w;
                if (((kk ^ prefix) & pmask) == 0)   // LOP3 + ISETP
                    atomicAdd(&hist[(kk >> shift) & 0xFFu], 1);
            }
        }
        __syncthreads();
        binsearch(remk);
        __syncthreads();
        prefix |= s_bin << shift;
        remk = s_remk;
        if (pass < 3) {
            hist[tid] = 0;
            __syncthreads();
        }
    }

    const uint32_t thr = prefix;       // exact KSEL-th largest key
    const int neq = s_neq;             // count of keys == thr (last pass hist)
    const bool allt = (neq == remk);   // all ties included (the ~always case)

    // ---- output: sigmoid for selected, 0 otherwise (128-bit coalesced) ----
    float* __restrict__ orow = out + (size_t)row * D;
    #pragma unroll
    for (int j = 0; j < 4; ++j) {
        int v = tid + T * j;
        uint4 k = reinterpret_cast<const uint4*>(skey)[v];
        float4 r;
        #pragma unroll
        for (int e = 0; e < 4; ++e) {
            uint32_t kk = (e == 0) ? k.x : (e == 1) ? k.y : (e == 2) ? k.z : k.w;
            float f = 0.0f;
            if (kk >= thr) {                     // ~64/4096 elements
                bool inc = (kk > thr) || allt;
                if (!inc) {                      // exact tie-break, ~never taken
                    int idx = 4 * v + e;
                    int rk = 0;
                    for (int q = 0; q < idx; ++q) rk += (skey[q] == thr);
                    inc = (rk < remk);           // lowest-index ties first
                }
                if (inc) f = sigm(k2f(kk));
            }
            ((float*)&r)[e] = f;
        }
        reinterpret_cast<float4*>(orow)[v] = r;
    }
}

extern "C" void kernel_launch(void* const* d_in, const int* in_sizes, int n_in,
                              void* d_out, int out_size) {
    const float* x = (const float*)d_in[0];
    float* out = (float*)d_out;
    int rows = in_sizes[0] / D;
    topk_sigmoid_kernel<<<rows, T>>>(x, out);
}